// round 15
// baseline (speedup 1.0000x reference)
#include <cuda_runtime.h>
#include <cuda_bf16.h>
#include <math.h>
#include <stdint.h>

#define EM   4
#define BN_  8
#define CM   896
#define HM   448
#define KM   512
#define G4H  1792

static const float ALPHAF = 5e-4f;

__device__ float g_W4[2 * 2 * HM * G4H];
__device__ float g_X0[BN_ * EM * CM];
__device__ float g_X1[BN_ * EM * CM];
__device__ float g_X2[BN_ * EM * CM];
__device__ float g_Gin[2 * BN_ * EM * G4H];
__device__ float g_G[BN_ * KM * KM];
__device__ float g_w[BN_ * KM];
__device__ float g_wU[BN_ * KM];
__device__ float g_cc[BN_ * KM];
__device__ float g_klp[BN_];

__device__ __forceinline__ float clampf(float v, float lo, float hi) {
    return fminf(fmaxf(v, lo), hi);
}
__device__ __forceinline__ uint32_t smem_u32(const void* p) {
    uint32_t a;
    asm("{ .reg .u64 t; cvta.to.shared.u64 t, %1; cvt.u32.u64 %0, t; }"
        : "=r"(a) : "l"(p));
    return a;
}
__device__ __forceinline__ void ldsm_x4(uint32_t* r, uint32_t addr) {
    asm volatile("ldmatrix.sync.aligned.m8n8.x4.shared.b16 {%0,%1,%2,%3}, [%4];"
        : "=r"(r[0]), "=r"(r[1]), "=r"(r[2]), "=r"(r[3]) : "r"(addr));
}
__device__ __forceinline__ void mma16816(float* c, const uint32_t* a,
                                         const uint32_t* b) {
    asm volatile(
        "mma.sync.aligned.m16n8k16.row.col.f32.bf16.bf16.f32 "
        "{%0,%1,%2,%3}, {%4,%5,%6,%7}, {%8,%9}, {%0,%1,%2,%3};"
        : "+f"(c[0]), "+f"(c[1]), "+f"(c[2]), "+f"(c[3])
        : "r"(a[0]), "r"(a[1]), "r"(a[2]), "r"(a[3]), "r"(b[0]), "r"(b[1]));
}
__device__ __forceinline__ void split4_store(__nv_bfloat16* H, __nv_bfloat16* L,
                                             int off, float4 v)
{
    __nv_bfloat162 h01, h23, l01, l23;
    h01.x = __float2bfloat16_rn(v.x);  h01.y = __float2bfloat16_rn(v.y);
    h23.x = __float2bfloat16_rn(v.z);  h23.y = __float2bfloat16_rn(v.w);
    l01.x = __float2bfloat16_rn(v.x - __bfloat162float(h01.x));
    l01.y = __float2bfloat16_rn(v.y - __bfloat162float(h01.y));
    l23.x = __float2bfloat16_rn(v.z - __bfloat162float(h23.x));
    l23.y = __float2bfloat16_rn(v.w - __bfloat162float(h23.y));
    *(__nv_bfloat162*)(H + off)     = h01;
    *(__nv_bfloat162*)(H + off + 2) = h23;
    *(__nv_bfloat162*)(L + off)     = l01;
    *(__nv_bfloat162*)(L + off + 2) = l23;
}

#define AS_STRIDE 72
#define A_TILE (128 * AS_STRIDE)
#define SYRK_SMEM (4 * A_TILE * 2)

__global__ void __launch_bounds__(256, 1)
syrk_kernel(const float* __restrict__ M, float* __restrict__ G)
{
    extern __shared__ __nv_bfloat16 sm[];
    __nv_bfloat16* sAh = sm;
    __nv_bfloat16* sAl = sm + A_TILE;
    __nv_bfloat16* sBh = sm + 2 * A_TILE;
    __nv_bfloat16* sBl = sm + 3 * A_TILE;

    int tid = threadIdx.x, wid = tid >> 5, lane = tid & 31;
    size_t bz = blockIdx.z;
    M += bz * (size_t)KM * CM;
    size_t cbase = bz * (size_t)KM * KM;

    int rowBase = blockIdx.y * 128, colBase = blockIdx.x * 128;
    int dup = (rowBase == colBase);
    int warpRow = (wid >> 2) * 64;
    int warpCol = (wid & 3) * 32;

    float acc[4][4][4];
#pragma unroll
    for (int i = 0; i < 4; i++)
#pragma unroll
        for (int j = 0; j < 4; j++)
#pragma unroll
            for (int q = 0; q < 4; q++) acc[i][j][q] = 0.f;

    uint32_t uAh = smem_u32(sAh), uAl = smem_u32(sAl);
    uint32_t uBh = dup ? uAh : smem_u32(sBh);
    uint32_t uBl = dup ? uAl : smem_u32(sBl);

    for (int c = 0; c < (CM >> 6); c++) {
        int k0 = c << 6;
#pragma unroll
        for (int i = 0; i < 8; i++) {
            int e = tid + (i << 8);
            int r = e >> 4;
            int col = (e & 15) << 2;
            int so = r * AS_STRIDE + col;
            float4 va = *(const float4*)(M + (size_t)(rowBase + r) * CM + k0 + col);
            split4_store(sAh, sAl, so, va);
            if (!dup) {
                float4 vb = *(const float4*)(M + (size_t)(colBase + r) * CM + k0 + col);
                split4_store(sBh, sBl, so, vb);
            }
        }
        __syncthreads();

#pragma unroll
        for (int ks = 0; ks < 4; ks++) {
            int kk = ks << 4;
            uint32_t ah[4][4], al[4][4], bh[4][2], bl[4][2];
            int arow = warpRow + (lane & 15);
            int akc  = kk + ((lane >> 4) << 3);
#pragma unroll
            for (int mi = 0; mi < 4; mi++) {
                uint32_t off = (uint32_t)((arow + mi * 16) * AS_STRIDE + akc) * 2;
                ldsm_x4(ah[mi], uAh + off);
                ldsm_x4(al[mi], uAl + off);
            }
            int brow = (lane & 7) + (((lane >> 4) & 1) << 3);
            int bkc  = kk + (((lane >> 3) & 1) << 3);
#pragma unroll
            for (int nt = 0; nt < 2; nt++) {
                uint32_t off = (uint32_t)((warpCol + nt * 16 + brow) * AS_STRIDE
                                          + bkc) * 2;
                uint32_t rh[4], rl[4];
                ldsm_x4(rh, uBh + off);
                ldsm_x4(rl, uBl + off);
                bh[2 * nt][0] = rh[0]; bh[2 * nt][1] = rh[1];
                bh[2 * nt + 1][0] = rh[2]; bh[2 * nt + 1][1] = rh[3];
                bl[2 * nt][0] = rl[0]; bl[2 * nt][1] = rl[1];
                bl[2 * nt + 1][0] = rl[2]; bl[2 * nt + 1][1] = rl[3];
            }
#pragma unroll
            for (int mi = 0; mi < 4; mi++)
#pragma unroll
                for (int ni = 0; ni < 4; ni++) {
                    mma16816(acc[mi][ni], ah[mi], bh[ni]);
                    mma16816(acc[mi][ni], ah[mi], bl[ni]);
                    mma16816(acc[mi][ni], al[mi], bh[ni]);
                }
        }
        __syncthreads();
    }

    int r0 = rowBase + warpRow + (lane >> 2);
    int c0 = colBase + warpCol + ((lane & 3) << 1);
#pragma unroll
    for (int mi = 0; mi < 4; mi++) {
#pragma unroll
        for (int ni = 0; ni < 4; ni++) {
            float* a = acc[mi][ni];
            size_t i0 = cbase + (size_t)(r0 + mi * 16) * KM + c0 + ni * 8;
            size_t i1 = i0 + (size_t)8 * KM;
            *(float2*)(G + i0) = make_float2(a[0], a[1]);
            *(float2*)(G + i1) = make_float2(a[2], a[3]);
        }
    }
}

// ===== fused addressing (1024 threads): w = q3(G)·(mean·zn); wU; sigma; c ==
__global__ void __launch_bounds__(1024, 1)
addr_kernel(const float* __restrict__ mean, const float* __restrict__ noise,
            const float* __restrict__ G, const float* __restrict__ cov, int t)
{
    int b = blockIdx.x, tid = threadIdx.x;
    int lane = tid & 31, wrp = tid >> 5;
    int col = tid & 511, half = tid >> 9;
    __shared__ float zn[CM];
    __shared__ float yv[KM];
    __shared__ float ws[KM];
    __shared__ float part[1024];
    __shared__ float red[KM];

    const float* zr = g_X2 + ((size_t)b * EM + t) * CM;
    const float* nr = noise + ((size_t)t * BN_ + b) * CM;
    for (int c = tid; c < CM; c += 1024)
        zn[c] = zr[c] + 0.1f * nr[c];
    __syncthreads();

    // u = mean · zn : 32 warps x 16 rows each
    const float* mb = mean + (size_t)b * KM * CM;
#pragma unroll 2
    for (int rr = 0; rr < 16; rr++) {
        int r = wrp * 16 + rr;
        const float* mr = mb + (size_t)r * CM;
        float s = 0.f;
        for (int c = lane; c < CM; c += 32)
            s = fmaf(mr[c], zn[c], s);
#pragma unroll
        for (int o = 16; o; o >>= 1)
            s += __shfl_down_sync(0xffffffffu, s, o);
        if (lane == 0) yv[r] = s;
    }
    __syncthreads();

    // 7 serial matvecs, j-loop split across halves (256 each)
    float yk = 0.f, wacc = 0.f;
    if (half == 0) { yk = yv[col]; wacc = yk; }
    const float* Gb = G + (size_t)b * KM * KM + col;
    int j0 = half << 8;
    for (int it = 0; it < 7; it++) {
        float s = 0.f;
#pragma unroll 16
        for (int j = j0; j < j0 + 256; j++)
            s = fmaf(Gb[(size_t)j * KM], yv[j], s);
        part[tid] = s;
        __syncthreads();
        if (half == 0) {
            float stot = part[col] + part[col + 512];
            yk = yk - ALPHAF * stot;
            wacc += yk;
            yv[col] = yk;
        }
        __syncthreads();
    }
    if (half == 0) {
        float wv = ALPHAF * wacc;
        ws[col] = wv;
        g_w[b * KM + col] = wv;
    }
    __syncthreads();

    // wU[j] = sum_k w[k] cov[k][j], split across halves
    const float* cb = cov + (size_t)b * KM * KM + col;
    float wp = 0.f;
#pragma unroll 16
    for (int k = j0; k < j0 + 256; k++)
        wp = fmaf(ws[k], cb[(size_t)k * KM], wp);
    part[tid] = wp;
    __syncthreads();
    float wu = 0.f;
    if (half == 0) {
        wu = part[col] + part[col + 512];
        g_wU[b * KM + col] = wu;
        red[col] = ws[col] * wu;
    }
    __syncthreads();
    for (int s = 256; s > 0; s >>= 1) {
        if (tid < s) red[tid] += red[tid + s];
        __syncthreads();
    }
    if (half == 0) {
        float sigma = fmaxf(red[0] + 0.01f, 1e-6f);
        g_cc[b * KM + col] = clampf(wu / sigma, -1000.f, 1000.f);
    }
}

__global__ void upd_kernel(float* __restrict__ mean, float* __restrict__ cov,
                           int t)
{
    int b = blockIdx.y;
    if (blockIdx.x < 7) {
        int c = blockIdx.x * 128 + threadIdx.x;
        __shared__ float ws[KM];
        __shared__ float cs[KM];
        for (int i = threadIdx.x; i < KM; i += 128) {
            ws[i] = g_w[b * KM + i];
            cs[i] = g_cc[b * KM + i];
        }
        __syncthreads();
        float* mb = mean + (size_t)b * KM * CM + c;
        float acc = 0.f;
#pragma unroll 8
        for (int k = 0; k < KM; k++)
            acc = fmaf(ws[k], mb[(size_t)k * CM], acc);
        float dv = clampf(g_X2[((size_t)b * EM + t) * CM + c] - acc,
                          -100.f, 100.f);
#pragma unroll 4
        for (int k = 0; k < KM; k++) {
            float m = mb[(size_t)k * CM] + cs[k] * dv;
            mb[(size_t)k * CM] = clampf(m, -1000.f, 1000.f);
        }
    } else {
        int i = blockIdx.x - 7;
        float ci = g_cc[b * KM + i];
        float wUi = g_wU[b * KM + i];
        size_t base = ((size_t)b * KM + i) * KM;
        for (int j = threadIdx.x; j < KM; j += 128) {
            float cj = g_cc[b * KM + j];
            float wUj = g_wU[b * KM + j];
            float v = cov[base + j] - 0.5f * (ci * wUj + cj * wUi);
            if (j == i) v = clampf(v, 0.001f, 1000.f) + 1e-6f;
            cov[base + j] = v;
        }
    }
}

__global__ void w4all_kernel(const float* __restrict__ Whh0,
                             const float* __restrict__ Whh1,
                             float* __restrict__ out)
{
    __shared__ float tile[32][33];
    int zidx = blockIdx.z;
    int layer = zidx >> 1, d = zidx & 1;
    const float* Whh = (layer ? Whh1 : Whh0) + (size_t)d * G4H * HM;
    float* ob = out + (size_t)zidx * HM * G4H;
    int cb = blockIdx.x * 32;
    int rb = blockIdx.y * 32;
    int x = threadIdx.x, y = threadIdx.y;
#pragma unroll
    for (int i = 0; i < 4; i++) {
        int r = rb + y + i * 8;
        tile[y + i * 8][x] = Whh[(size_t)r * HM + cb + x];
    }
    __syncthreads();
#pragma unroll
    for (int i = 0; i < 4; i++) {
        int hp = cb + y + i * 8;
        int j  = rb + x;
        int u = j % HM, g = j / HM;
        ob[(size_t)hp * G4H + u * 4 + g] = tile[x][y + i * 8];
    }
}

__global__ void initall_kernel(const float* __restrict__ mm,
                               const float* __restrict__ z,
                               float* __restrict__ mean,
                               float* __restrict__ cov)
{
    int bx = blockIdx.x, b = blockIdx.y;
    if (bx < 1792) {
        int idx = bx * 256 + threadIdx.x;
        mean[(size_t)b * KM * CM + idx] = mm[idx];
    } else if (bx < 2816) {
        int idx = (bx - 1792) * 256 + threadIdx.x;
        int i = idx / KM, j = idx % KM;
        cov[(size_t)b * KM * KM + idx] = (i == j) ? 1.000001f : 0.f;
    } else if (b == 0) {
        int idx = (bx - 2816) * 256 + threadIdx.x;
        if (idx < BN_ * EM * CM) {
            int c = idx % CM;
            int m = idx / CM;
            int t = m % EM;
            int bb = m / EM;
            g_X0[idx] = z[((size_t)t * BN_ + bb) * CM + c];
        }
    }
}

__global__ void inproj_kernel(const float* __restrict__ X,
                              const float* __restrict__ Wih,
                              const float* __restrict__ bias)
{
    int d = blockIdx.y;
    int jb = blockIdx.x * 64;
    __shared__ float Xs[32][33];
    __shared__ float Ws[64][33];
    int tid = threadIdx.x;
    int tx = tid & 31, ty = tid >> 5;
    float acc[4][2] = {{0.f,0.f},{0.f,0.f},{0.f,0.f},{0.f,0.f}};

    for (int c0 = 0; c0 < CM; c0 += 32) {
#pragma unroll
        for (int i = 0; i < 4; i++) {
            int e = tid + i * 256; int r = e >> 5, cc = e & 31;
            Xs[r][cc] = X[(size_t)r * CM + c0 + cc];
        }
#pragma unroll
        for (int i = 0; i < 8; i++) {
            int e = tid + i * 256; int r = e >> 5, cc = e & 31;
            Ws[r][cc] = Wih[((size_t)d * G4H + jb + r) * CM + c0 + cc];
        }
        __syncthreads();
#pragma unroll
        for (int kk = 0; kk < 32; kk++) {
            float w0 = Ws[tx * 2 + 0][kk];
            float w1 = Ws[tx * 2 + 1][kk];
#pragma unroll
            for (int mi = 0; mi < 4; mi++) {
                float xv = Xs[ty * 4 + mi][kk];
                acc[mi][0] = fmaf(xv, w0, acc[mi][0]);
                acc[mi][1] = fmaf(xv, w1, acc[mi][1]);
            }
        }
        __syncthreads();
    }
#pragma unroll
    for (int mi = 0; mi < 4; mi++)
#pragma unroll
        for (int ji = 0; ji < 2; ji++) {
            int m = ty * 4 + mi;
            int j = jb + tx * 2 + ji;
            g_Gin[((size_t)d * (BN_ * EM) + m) * G4H + j] = acc[mi][ji] + bias[d * G4H + j];
        }
}

// LSTM: 4 fused steps, 8-deep float4 W prefetch pipeline (order-preserving)
__global__ void lstm_steps_kernel(float* __restrict__ Xout, int layer)
{
    int b = blockIdx.x, d = blockIdx.y, tid = threadIdx.x;  // 448 threads
    __shared__ float hs[HM];
    float h = 0.f, cst = 0.f;
    const float4* W4p = (const float4*)(g_W4 +
        ((size_t)(layer * 2 + d)) * HM * G4H) + tid;   // row stride 448 float4

    for (int s = 0; s < EM; s++) {
        int t = (d == 0) ? s : (EM - 1 - s);
        hs[tid] = h;
        __syncthreads();

        float a0 = 0.f, a1 = 0.f, a2 = 0.f, a3 = 0.f;
        float4 buf[8];
#pragma unroll
        for (int i = 0; i < 8; i++)
            buf[i] = W4p[(size_t)i * 448];

        for (int hp = 0; hp < HM; hp += 8) {
            bool more = (hp + 8) < HM;
#pragma unroll
            for (int i = 0; i < 8; i++) {
                float hv = hs[hp + i];
                float4 wv = buf[i];
                if (more) buf[i] = W4p[(size_t)(hp + 8 + i) * 448];
                a0 = fmaf(wv.x, hv, a0);
                a1 = fmaf(wv.y, hv, a1);
                a2 = fmaf(wv.z, hv, a2);
                a3 = fmaf(wv.w, hv, a3);
            }
        }
        const float* gi = g_Gin + ((size_t)d * (BN_ * EM) + b * EM + t) * G4H + tid;
        a0 += gi[0 * HM]; a1 += gi[1 * HM]; a2 += gi[2 * HM]; a3 += gi[3 * HM];

        float si = 1.f / (1.f + expf(-a0));
        float sf = 1.f / (1.f + expf(-a1));
        float so = 1.f / (1.f + expf(-a3));
        cst = sf * cst + si * tanhf(a2);
        h = so * tanhf(cst);
        Xout[((size_t)b * EM + t) * CM + d * HM + tid] = h;
        __syncthreads();
    }
}

__global__ void kl_partial_kernel(const float* __restrict__ mean,
                                  const float* __restrict__ cov,
                                  const float* __restrict__ mm)
{
    int b = blockIdx.x, tid = threadIdx.x;
    const float pd = 1.0f + 1e-6f;
    const float lpd = logf(pd);
    float s1 = 0.f, s4 = 0.f, s2 = 0.f;

    for (int k = tid; k < KM; k += 256) {
        float q = clampf(cov[((size_t)b * KM + k) * KM + k], 0.001f, 1e6f);
        s1 += clampf(q / pd, 1e-6f, 1000.f);
        s4 += clampf(lpd - logf(q), -10.f, 10.f);
    }
    const float* mb = mean + (size_t)b * KM * CM;
    for (int idx = tid; idx < KM * CM; idx += 256) {
        float d = mb[idx] - mm[idx];
        s2 += fminf(d * d, 1000.f);
    }
    s2 /= pd;

    __shared__ float r1[256], r2[256], r4[256];
    r1[tid] = s1; r2[tid] = s2; r4[tid] = s4;
    __syncthreads();
    for (int s = 128; s > 0; s >>= 1) {
        if (tid < s) { r1[tid] += r1[tid + s]; r2[tid] += r2[tid + s]; r4[tid] += r4[tid + s]; }
        __syncthreads();
    }
    if (tid == 0) {
        float t1 = clampf((float)CM * r1[0], -1e6f, 1e6f);
        float t2 = clampf(r2[0], -1e6f, 1e6f);
        float t4 = clampf((float)CM * r4[0], -1e6f, 1e6f);
        g_klp[b] = t1 + t2 + t4 - (float)(CM * KM);
    }
}

__global__ void kl_final_kernel(float* __restrict__ dkl)
{
    float s = 0.f;
    for (int b = 0; b < BN_; b++) s += g_klp[b];
    dkl[0] = s * (1.0f / BN_);
}

extern "C" void kernel_launch(void* const* d_in, const int* in_sizes, int n_in,
                              void* d_out, int out_size)
{
    const float* z    = (const float*)d_in[0];
    const float* mm   = (const float*)d_in[1];
    const float* nois = (const float*)d_in[2];
    const float* Wih0 = (const float*)d_in[3];
    const float* Whh0 = (const float*)d_in[4];
    const float* b0   = (const float*)d_in[5];
    const float* Wih1 = (const float*)d_in[6];
    const float* Whh1 = (const float*)d_in[7];
    const float* b1   = (const float*)d_in[8];

    float* out_mean = (float*)d_out;
    float* out_cov  = out_mean + (size_t)BN_ * KM * CM;
    float* out_dkl  = out_cov + (size_t)BN_ * KM * KM;

    float *pW4, *pX0, *pX1, *pX2, *pG;
    cudaGetSymbolAddress((void**)&pW4, g_W4);
    cudaGetSymbolAddress((void**)&pX0, g_X0);
    cudaGetSymbolAddress((void**)&pX1, g_X1);
    cudaGetSymbolAddress((void**)&pX2, g_X2);
    cudaGetSymbolAddress((void**)&pG,  g_G);

    cudaFuncSetAttribute(syrk_kernel,
                         cudaFuncAttributeMaxDynamicSharedMemorySize, SYRK_SMEM);

    w4all_kernel<<<dim3(14, 56, 4), dim3(32, 8)>>>(Whh0, Whh1, pW4);
    initall_kernel<<<dim3(2816 + 112, BN_), 256>>>(mm, z, out_mean, out_cov);

    inproj_kernel<<<dim3(G4H / 64, 2), 256>>>(pX0, Wih0, b0);
    lstm_steps_kernel<<<dim3(BN_, 2), HM>>>(pX1, 0);
    inproj_kernel<<<dim3(G4H / 64, 2), 256>>>(pX1, Wih1, b1);
    lstm_steps_kernel<<<dim3(BN_, 2), HM>>>(pX2, 1);

    for (int t = 0; t < EM; t++) {
        syrk_kernel<<<dim3(KM / 128, KM / 128, BN_), 256, SYRK_SMEM>>>(
            out_mean, pG);
        addr_kernel<<<BN_, 1024>>>(out_mean, nois, pG, out_cov, t);
        upd_kernel<<<dim3(7 + KM, BN_), 128>>>(out_mean, out_cov, t);
    }

    kl_partial_kernel<<<BN_, 256>>>(out_mean, out_cov, mm);
    kl_final_kernel<<<1, 1>>>(out_dkl);
}

// round 16
// speedup vs baseline: 1.1504x; 1.1504x over previous
#include <cuda_runtime.h>
#include <cuda_bf16.h>
#include <math.h>
#include <stdint.h>

#define EM   4
#define BN_  8
#define CM   896
#define HM   448
#define KM   512
#define G4H  1792

static const float ALPHAF = 5e-4f;

__device__ float g_W4[2 * 2 * HM * G4H];
__device__ float g_X0[BN_ * EM * CM];
__device__ float g_X1[BN_ * EM * CM];
__device__ float g_X2[BN_ * EM * CM];
__device__ float g_Gin[2 * BN_ * EM * G4H];
__device__ float g_G[BN_ * KM * KM];
__device__ float g_w[BN_ * KM];
__device__ float g_wU[BN_ * KM];
__device__ float g_cc[BN_ * KM];
__device__ float g_klp[BN_];

__device__ __forceinline__ float clampf(float v, float lo, float hi) {
    return fminf(fmaxf(v, lo), hi);
}
__device__ __forceinline__ uint32_t smem_u32(const void* p) {
    uint32_t a;
    asm("{ .reg .u64 t; cvta.to.shared.u64 t, %1; cvt.u32.u64 %0, t; }"
        : "=r"(a) : "l"(p));
    return a;
}
__device__ __forceinline__ void ldsm_x4(uint32_t* r, uint32_t addr) {
    asm volatile("ldmatrix.sync.aligned.m8n8.x4.shared.b16 {%0,%1,%2,%3}, [%4];"
        : "=r"(r[0]), "=r"(r[1]), "=r"(r[2]), "=r"(r[3]) : "r"(addr));
}
__device__ __forceinline__ void mma16816(float* c, const uint32_t* a,
                                         const uint32_t* b) {
    asm volatile(
        "mma.sync.aligned.m16n8k16.row.col.f32.bf16.bf16.f32 "
        "{%0,%1,%2,%3}, {%4,%5,%6,%7}, {%8,%9}, {%0,%1,%2,%3};"
        : "+f"(c[0]), "+f"(c[1]), "+f"(c[2]), "+f"(c[3])
        : "r"(a[0]), "r"(a[1]), "r"(a[2]), "r"(a[3]), "r"(b[0]), "r"(b[1]));
}
__device__ __forceinline__ void split4_store(__nv_bfloat16* H, __nv_bfloat16* L,
                                             int off, float4 v)
{
    __nv_bfloat162 h01, h23, l01, l23;
    h01.x = __float2bfloat16_rn(v.x);  h01.y = __float2bfloat16_rn(v.y);
    h23.x = __float2bfloat16_rn(v.z);  h23.y = __float2bfloat16_rn(v.w);
    l01.x = __float2bfloat16_rn(v.x - __bfloat162float(h01.x));
    l01.y = __float2bfloat16_rn(v.y - __bfloat162float(h01.y));
    l23.x = __float2bfloat16_rn(v.z - __bfloat162float(h23.x));
    l23.y = __float2bfloat16_rn(v.w - __bfloat162float(h23.y));
    *(__nv_bfloat162*)(H + off)     = h01;
    *(__nv_bfloat162*)(H + off + 2) = h23;
    *(__nv_bfloat162*)(L + off)     = l01;
    *(__nv_bfloat162*)(L + off + 2) = l23;
}

#define AS_STRIDE 72
#define A_TILE (128 * AS_STRIDE)
#define SYRK_SMEM (4 * A_TILE * 2)     // 73728 B; also covers 128*132*4 staging

// SYRK computing only lower-triangle tiles; off-diagonal tiles mirrored via
// smem-staged transposed coalesced store.
__global__ void __launch_bounds__(256, 1)
syrk_kernel(const float* __restrict__ M, float* __restrict__ G)
{
    extern __shared__ __nv_bfloat16 sm[];
    __nv_bfloat16* sAh = sm;
    __nv_bfloat16* sAl = sm + A_TILE;
    __nv_bfloat16* sBh = sm + 2 * A_TILE;
    __nv_bfloat16* sBl = sm + 3 * A_TILE;

    int tid = threadIdx.x, wid = tid >> 5, lane = tid & 31;
    size_t bz = blockIdx.z;
    M += bz * (size_t)KM * CM;
    size_t cbase = bz * (size_t)KM * KM;

    // map linear tile index (0..9) -> (ti >= tj) lower triangle of 4x4
    int p = blockIdx.x;
    int ti = 0;
    while ((ti + 1) * (ti + 2) / 2 <= p) ti++;
    int tj = p - ti * (ti + 1) / 2;

    int rowBase = ti * 128, colBase = tj * 128;
    int dup = (ti == tj);
    int warpRow = (wid >> 2) * 64;
    int warpCol = (wid & 3) * 32;

    float acc[4][4][4];
#pragma unroll
    for (int i = 0; i < 4; i++)
#pragma unroll
        for (int j = 0; j < 4; j++)
#pragma unroll
            for (int q = 0; q < 4; q++) acc[i][j][q] = 0.f;

    uint32_t uAh = smem_u32(sAh), uAl = smem_u32(sAl);
    uint32_t uBh = dup ? uAh : smem_u32(sBh);
    uint32_t uBl = dup ? uAl : smem_u32(sBl);

    for (int c = 0; c < (CM >> 6); c++) {
        int k0 = c << 6;
#pragma unroll
        for (int i = 0; i < 8; i++) {
            int e = tid + (i << 8);
            int r = e >> 4;
            int col = (e & 15) << 2;
            int so = r * AS_STRIDE + col;
            float4 va = *(const float4*)(M + (size_t)(rowBase + r) * CM + k0 + col);
            split4_store(sAh, sAl, so, va);
            if (!dup) {
                float4 vb = *(const float4*)(M + (size_t)(colBase + r) * CM + k0 + col);
                split4_store(sBh, sBl, so, vb);
            }
        }
        __syncthreads();

#pragma unroll
        for (int ks = 0; ks < 4; ks++) {
            int kk = ks << 4;
            uint32_t ah[4][4], al[4][4], bh[4][2], bl[4][2];
            int arow = warpRow + (lane & 15);
            int akc  = kk + ((lane >> 4) << 3);
#pragma unroll
            for (int mi = 0; mi < 4; mi++) {
                uint32_t off = (uint32_t)((arow + mi * 16) * AS_STRIDE + akc) * 2;
                ldsm_x4(ah[mi], uAh + off);
                ldsm_x4(al[mi], uAl + off);
            }
            int brow = (lane & 7) + (((lane >> 4) & 1) << 3);
            int bkc  = kk + (((lane >> 3) & 1) << 3);
#pragma unroll
            for (int nt = 0; nt < 2; nt++) {
                uint32_t off = (uint32_t)((warpCol + nt * 16 + brow) * AS_STRIDE
                                          + bkc) * 2;
                uint32_t rh[4], rl[4];
                ldsm_x4(rh, uBh + off);
                ldsm_x4(rl, uBl + off);
                bh[2 * nt][0] = rh[0]; bh[2 * nt][1] = rh[1];
                bh[2 * nt + 1][0] = rh[2]; bh[2 * nt + 1][1] = rh[3];
                bl[2 * nt][0] = rl[0]; bl[2 * nt][1] = rl[1];
                bl[2 * nt + 1][0] = rl[2]; bl[2 * nt + 1][1] = rl[3];
            }
#pragma unroll
            for (int mi = 0; mi < 4; mi++)
#pragma unroll
                for (int ni = 0; ni < 4; ni++) {
                    mma16816(acc[mi][ni], ah[mi], bh[ni]);
                    mma16816(acc[mi][ni], ah[mi], bl[ni]);
                    mma16816(acc[mi][ni], al[mi], bh[ni]);
                }
        }
        __syncthreads();
    }

    // ---- epilogue: direct store of (ti,tj) tile ----
    int r0l = warpRow + (lane >> 2);                // local row in tile
    int c0l = warpCol + ((lane & 3) << 1);          // local col in tile
#pragma unroll
    for (int mi = 0; mi < 4; mi++) {
#pragma unroll
        for (int ni = 0; ni < 4; ni++) {
            float* a = acc[mi][ni];
            size_t i0 = cbase + (size_t)(rowBase + r0l + mi * 16) * KM
                        + colBase + c0l + ni * 8;
            size_t i1 = i0 + (size_t)8 * KM;
            *(float2*)(G + i0) = make_float2(a[0], a[1]);
            *(float2*)(G + i1) = make_float2(a[2], a[3]);
        }
    }

    // ---- mirror for off-diagonal tiles: stage -> transposed coalesced ----
    if (!dup) {
        float* st = (float*)sm;                     // 128 x 132 floats = 67.6KB
#pragma unroll
        for (int mi = 0; mi < 4; mi++) {
#pragma unroll
            for (int ni = 0; ni < 4; ni++) {
                float* a = acc[mi][ni];
                int rr = r0l + mi * 16;
                int cc = c0l + ni * 8;
                st[rr * 132 + cc]           = a[0];
                st[rr * 132 + cc + 1]       = a[1];
                st[(rr + 8) * 132 + cc]     = a[2];
                st[(rr + 8) * 132 + cc + 1] = a[3];
            }
        }
        __syncthreads();
        // G[colBase + rr][rowBase + cc] = st[cc][rr]
#pragma unroll
        for (int i = 0; i < 16; i++) {
            int e = tid + (i << 8);
            int rr = e >> 5;                        // 0..127 (out row)
            int c4 = (e & 31) << 2;                 // 0..124 (out col, 4-wide)
            float4 v;
            v.x = st[(c4 + 0) * 132 + rr];
            v.y = st[(c4 + 1) * 132 + rr];
            v.z = st[(c4 + 2) * 132 + rr];
            v.w = st[(c4 + 3) * 132 + rr];
            *(float4*)(G + cbase + (size_t)(colBase + rr) * KM + rowBase + c4) = v;
        }
    }
}

// ===== fused addressing (512 threads, R14-proven) =========================
__global__ void __launch_bounds__(512, 1)
addr_kernel(const float* __restrict__ mean, const float* __restrict__ noise,
            const float* __restrict__ G, const float* __restrict__ cov, int t)
{
    int b = blockIdx.x, tid = threadIdx.x;
    int lane = tid & 31, wrp = tid >> 5;
    __shared__ float zn[CM];
    __shared__ float yv[KM];
    __shared__ float ws[KM];
    __shared__ float red[KM];

    const float* zr = g_X2 + ((size_t)b * EM + t) * CM;
    const float* nr = noise + ((size_t)t * BN_ + b) * CM;
    for (int c = tid; c < CM; c += KM)
        zn[c] = zr[c] + 0.1f * nr[c];
    __syncthreads();

    const float* mb = mean + (size_t)b * KM * CM;
#pragma unroll 4
    for (int rr = 0; rr < 32; rr++) {
        int r = wrp * 32 + rr;
        const float* mr = mb + (size_t)r * CM;
        float s = 0.f;
        for (int c = lane; c < CM; c += 32)
            s = fmaf(mr[c], zn[c], s);
#pragma unroll
        for (int o = 16; o; o >>= 1)
            s += __shfl_down_sync(0xffffffffu, s, o);
        if (lane == 0) yv[r] = s;
    }
    __syncthreads();

    float yk = yv[tid], wacc = yk;
    const float* Gb = G + (size_t)b * KM * KM + tid;
    for (int it = 0; it < 7; it++) {
        float s = 0.f;
#pragma unroll 8
        for (int j = 0; j < KM; j++)
            s = fmaf(Gb[(size_t)j * KM], yv[j], s);
        yk = yk - ALPHAF * s;
        wacc += yk;
        __syncthreads();
        yv[tid] = yk;
        __syncthreads();
    }
    float wv = ALPHAF * wacc;
    ws[tid] = wv;
    g_w[b * KM + tid] = wv;
    __syncthreads();

    const float* cb = cov + (size_t)b * KM * KM + tid;
    float wu = 0.f;
#pragma unroll 8
    for (int k = 0; k < KM; k++)
        wu = fmaf(ws[k], cb[(size_t)k * KM], wu);
    g_wU[b * KM + tid] = wu;

    red[tid] = wv * wu;
    __syncthreads();
    for (int s = 256; s > 0; s >>= 1) {
        if (tid < s) red[tid] += red[tid + s];
        __syncthreads();
    }
    float sigma = fmaxf(red[0] + 0.01f, 1e-6f);
    g_cc[b * KM + tid] = clampf(wu / sigma, -1000.f, 1000.f);
}

__global__ void upd_kernel(float* __restrict__ mean, float* __restrict__ cov,
                           int t)
{
    int b = blockIdx.y;
    if (blockIdx.x < 7) {
        int c = blockIdx.x * 128 + threadIdx.x;
        __shared__ float ws[KM];
        __shared__ float cs[KM];
        for (int i = threadIdx.x; i < KM; i += 128) {
            ws[i] = g_w[b * KM + i];
            cs[i] = g_cc[b * KM + i];
        }
        __syncthreads();
        float* mb = mean + (size_t)b * KM * CM + c;
        float acc = 0.f;
#pragma unroll 8
        for (int k = 0; k < KM; k++)
            acc = fmaf(ws[k], mb[(size_t)k * CM], acc);
        float dv = clampf(g_X2[((size_t)b * EM + t) * CM + c] - acc,
                          -100.f, 100.f);
#pragma unroll 4
        for (int k = 0; k < KM; k++) {
            float m = mb[(size_t)k * CM] + cs[k] * dv;
            mb[(size_t)k * CM] = clampf(m, -1000.f, 1000.f);
        }
    } else {
        int i = blockIdx.x - 7;
        float ci = g_cc[b * KM + i];
        float wUi = g_wU[b * KM + i];
        size_t base = ((size_t)b * KM + i) * KM;
        for (int j = threadIdx.x; j < KM; j += 128) {
            float cj = g_cc[b * KM + j];
            float wUj = g_wU[b * KM + j];
            float v = cov[base + j] - 0.5f * (ci * wUj + cj * wUi);
            if (j == i) v = clampf(v, 0.001f, 1000.f) + 1e-6f;
            cov[base + j] = v;
        }
    }
}

__global__ void w4all_kernel(const float* __restrict__ Whh0,
                             const float* __restrict__ Whh1,
                             float* __restrict__ out)
{
    __shared__ float tile[32][33];
    int zidx = blockIdx.z;
    int layer = zidx >> 1, d = zidx & 1;
    const float* Whh = (layer ? Whh1 : Whh0) + (size_t)d * G4H * HM;
    float* ob = out + (size_t)zidx * HM * G4H;
    int cb = blockIdx.x * 32;
    int rb = blockIdx.y * 32;
    int x = threadIdx.x, y = threadIdx.y;
#pragma unroll
    for (int i = 0; i < 4; i++) {
        int r = rb + y + i * 8;
        tile[y + i * 8][x] = Whh[(size_t)r * HM + cb + x];
    }
    __syncthreads();
#pragma unroll
    for (int i = 0; i < 4; i++) {
        int hp = cb + y + i * 8;
        int j  = rb + x;
        int u = j % HM, g = j / HM;
        ob[(size_t)hp * G4H + u * 4 + g] = tile[x][y + i * 8];
    }
}

__global__ void initall_kernel(const float* __restrict__ mm,
                               const float* __restrict__ z,
                               float* __restrict__ mean,
                               float* __restrict__ cov)
{
    int bx = blockIdx.x, b = blockIdx.y;
    if (bx < 1792) {
        int idx = bx * 256 + threadIdx.x;
        mean[(size_t)b * KM * CM + idx] = mm[idx];
    } else if (bx < 2816) {
        int idx = (bx - 1792) * 256 + threadIdx.x;
        int i = idx / KM, j = idx % KM;
        cov[(size_t)b * KM * KM + idx] = (i == j) ? 1.000001f : 0.f;
    } else if (b == 0) {
        int idx = (bx - 2816) * 256 + threadIdx.x;
        if (idx < BN_ * EM * CM) {
            int c = idx % CM;
            int m = idx / CM;
            int t = m % EM;
            int bb = m / EM;
            g_X0[idx] = z[((size_t)t * BN_ + bb) * CM + c];
        }
    }
}

__global__ void inproj_kernel(const float* __restrict__ X,
                              const float* __restrict__ Wih,
                              const float* __restrict__ bias)
{
    int d = blockIdx.y;
    int jb = blockIdx.x * 64;
    __shared__ float Xs[32][33];
    __shared__ float Ws[64][33];
    int tid = threadIdx.x;
    int tx = tid & 31, ty = tid >> 5;
    float acc[4][2] = {{0.f,0.f},{0.f,0.f},{0.f,0.f},{0.f,0.f}};

    for (int c0 = 0; c0 < CM; c0 += 32) {
#pragma unroll
        for (int i = 0; i < 4; i++) {
            int e = tid + i * 256; int r = e >> 5, cc = e & 31;
            Xs[r][cc] = X[(size_t)r * CM + c0 + cc];
        }
#pragma unroll
        for (int i = 0; i < 8; i++) {
            int e = tid + i * 256; int r = e >> 5, cc = e & 31;
            Ws[r][cc] = Wih[((size_t)d * G4H + jb + r) * CM + c0 + cc];
        }
        __syncthreads();
#pragma unroll
        for (int kk = 0; kk < 32; kk++) {
            float w0 = Ws[tx * 2 + 0][kk];
            float w1 = Ws[tx * 2 + 1][kk];
#pragma unroll
            for (int mi = 0; mi < 4; mi++) {
                float xv = Xs[ty * 4 + mi][kk];
                acc[mi][0] = fmaf(xv, w0, acc[mi][0]);
                acc[mi][1] = fmaf(xv, w1, acc[mi][1]);
            }
        }
        __syncthreads();
    }
#pragma unroll
    for (int mi = 0; mi < 4; mi++)
#pragma unroll
        for (int ji = 0; ji < 2; ji++) {
            int m = ty * 4 + mi;
            int j = jb + tx * 2 + ji;
            g_Gin[((size_t)d * (BN_ * EM) + m) * G4H + j] = acc[mi][ji] + bias[d * G4H + j];
        }
}

// LSTM: 4 fused steps, 8-deep float4 W prefetch pipeline (R15 version, kept)
__global__ void lstm_steps_kernel(float* __restrict__ Xout, int layer)
{
    int b = blockIdx.x, d = blockIdx.y, tid = threadIdx.x;
    __shared__ float hs[HM];
    float h = 0.f, cst = 0.f;
    const float4* W4p = (const float4*)(g_W4 +
        ((size_t)(layer * 2 + d)) * HM * G4H) + tid;

    for (int s = 0; s < EM; s++) {
        int t = (d == 0) ? s : (EM - 1 - s);
        hs[tid] = h;
        __syncthreads();

        float a0 = 0.f, a1 = 0.f, a2 = 0.f, a3 = 0.f;
        float4 buf[8];
#pragma unroll
        for (int i = 0; i < 8; i++)
            buf[i] = W4p[(size_t)i * 448];

        for (int hp = 0; hp < HM; hp += 8) {
            bool more = (hp + 8) < HM;
#pragma unroll
            for (int i = 0; i < 8; i++) {
                float hv = hs[hp + i];
                float4 wv = buf[i];
                if (more) buf[i] = W4p[(size_t)(hp + 8 + i) * 448];
                a0 = fmaf(wv.x, hv, a0);
                a1 = fmaf(wv.y, hv, a1);
                a2 = fmaf(wv.z, hv, a2);
                a3 = fmaf(wv.w, hv, a3);
            }
        }
        const float* gi = g_Gin + ((size_t)d * (BN_ * EM) + b * EM + t) * G4H + tid;
        a0 += gi[0 * HM]; a1 += gi[1 * HM]; a2 += gi[2 * HM]; a3 += gi[3 * HM];

        float si = 1.f / (1.f + expf(-a0));
        float sf = 1.f / (1.f + expf(-a1));
        float so = 1.f / (1.f + expf(-a3));
        cst = sf * cst + si * tanhf(a2);
        h = so * tanhf(cst);
        Xout[((size_t)b * EM + t) * CM + d * HM + tid] = h;
        __syncthreads();
    }
}

__global__ void kl_partial_kernel(const float* __restrict__ mean,
                                  const float* __restrict__ cov,
                                  const float* __restrict__ mm)
{
    int b = blockIdx.x, tid = threadIdx.x;
    const float pd = 1.0f + 1e-6f;
    const float lpd = logf(pd);
    float s1 = 0.f, s4 = 0.f, s2 = 0.f;

    for (int k = tid; k < KM; k += 256) {
        float q = clampf(cov[((size_t)b * KM + k) * KM + k], 0.001f, 1e6f);
        s1 += clampf(q / pd, 1e-6f, 1000.f);
        s4 += clampf(lpd - logf(q), -10.f, 10.f);
    }
    const float* mb = mean + (size_t)b * KM * CM;
    for (int idx = tid; idx < KM * CM; idx += 256) {
        float d = mb[idx] - mm[idx];
        s2 += fminf(d * d, 1000.f);
    }
    s2 /= pd;

    __shared__ float r1[256], r2[256], r4[256];
    r1[tid] = s1; r2[tid] = s2; r4[tid] = s4;
    __syncthreads();
    for (int s = 128; s > 0; s >>= 1) {
        if (tid < s) { r1[tid] += r1[tid + s]; r2[tid] += r2[tid + s]; r4[tid] += r4[tid + s]; }
        __syncthreads();
    }
    if (tid == 0) {
        float t1 = clampf((float)CM * r1[0], -1e6f, 1e6f);
        float t2 = clampf(r2[0], -1e6f, 1e6f);
        float t4 = clampf((float)CM * r4[0], -1e6f, 1e6f);
        g_klp[b] = t1 + t2 + t4 - (float)(CM * KM);
    }
}

__global__ void kl_final_kernel(float* __restrict__ dkl)
{
    float s = 0.f;
    for (int b = 0; b < BN_; b++) s += g_klp[b];
    dkl[0] = s * (1.0f / BN_);
}

extern "C" void kernel_launch(void* const* d_in, const int* in_sizes, int n_in,
                              void* d_out, int out_size)
{
    const float* z    = (const float*)d_in[0];
    const float* mm   = (const float*)d_in[1];
    const float* nois = (const float*)d_in[2];
    const float* Wih0 = (const float*)d_in[3];
    const float* Whh0 = (const float*)d_in[4];
    const float* b0   = (const float*)d_in[5];
    const float* Wih1 = (const float*)d_in[6];
    const float* Whh1 = (const float*)d_in[7];
    const float* b1   = (const float*)d_in[8];

    float* out_mean = (float*)d_out;
    float* out_cov  = out_mean + (size_t)BN_ * KM * CM;
    float* out_dkl  = out_cov + (size_t)BN_ * KM * KM;

    float *pW4, *pX0, *pX1, *pX2, *pG;
    cudaGetSymbolAddress((void**)&pW4, g_W4);
    cudaGetSymbolAddress((void**)&pX0, g_X0);
    cudaGetSymbolAddress((void**)&pX1, g_X1);
    cudaGetSymbolAddress((void**)&pX2, g_X2);
    cudaGetSymbolAddress((void**)&pG,  g_G);

    cudaFuncSetAttribute(syrk_kernel,
                         cudaFuncAttributeMaxDynamicSharedMemorySize, SYRK_SMEM);

    w4all_kernel<<<dim3(14, 56, 4), dim3(32, 8)>>>(Whh0, Whh1, pW4);
    initall_kernel<<<dim3(2816 + 112, BN_), 256>>>(mm, z, out_mean, out_cov);

    inproj_kernel<<<dim3(G4H / 64, 2), 256>>>(pX0, Wih0, b0);
    lstm_steps_kernel<<<dim3(BN_, 2), HM>>>(pX1, 0);
    inproj_kernel<<<dim3(G4H / 64, 2), 256>>>(pX1, Wih1, b1);
    lstm_steps_kernel<<<dim3(BN_, 2), HM>>>(pX2, 1);

    for (int t = 0; t < EM; t++) {
        syrk_kernel<<<dim3(10, 1, BN_), 256, SYRK_SMEM>>>(out_mean, pG);
        addr_kernel<<<BN_, KM>>>(out_mean, nois, pG, out_cov, t);
        upd_kernel<<<dim3(7 + KM, BN_), 128>>>(out_mean, out_cov, t);
    }

    kl_partial_kernel<<<BN_, 256>>>(out_mean, out_cov, mm);
    kl_final_kernel<<<1, 1>>>(out_dkl);
}